// round 5
// baseline (speedup 1.0000x reference)
#include <cuda_runtime.h>
#include <cuda_bf16.h>
#include <cstdint>
#include <math.h>

#define NB 128
#define NL 4096
#define ND 128

// ---------------- scratch (device globals; no allocation) ----------------
__device__ float          g_qb[NB * ND];
__device__ __nv_bfloat16  g_Whi[ND * ND];
__device__ __nv_bfloat16  g_Wlo[ND * ND];
__device__ float          g_scores[NB * NL];

__device__ __forceinline__ uint32_t smem_u32(const void* p) {
    uint32_t a;
    asm("{ .reg .u64 t; cvta.to.shared.u64 t, %1; cvt.u32.u64 %0, t; }" : "=r"(a) : "l"(p));
    return a;
}

__device__ __forceinline__ void ldsm_x4(uint32_t& r0, uint32_t& r1, uint32_t& r2, uint32_t& r3,
                                        uint32_t addr) {
    asm volatile("ldmatrix.sync.aligned.m8n8.x4.shared.b16 {%0,%1,%2,%3}, [%4];"
                 : "=r"(r0), "=r"(r1), "=r"(r2), "=r"(r3) : "r"(addr));
}

__device__ __forceinline__ void mma16816(float* c, const uint32_t* a, const uint32_t* b) {
    asm volatile("mma.sync.aligned.m16n8k16.row.col.f32.bf16.bf16.f32 "
                 "{%0,%1,%2,%3}, {%4,%5,%6,%7}, {%8,%9}, {%0,%1,%2,%3};"
                 : "+f"(c[0]), "+f"(c[1]), "+f"(c[2]), "+f"(c[3])
                 : "r"(a[0]), "r"(a[1]), "r"(a[2]), "r"(a[3]), "r"(b[0]), "r"(b[1]));
}

// ============ kernel 0: qb = Wr2·(Wf target + b) + bias_r ; Wr1 -> hi/lo bf16 ============
__global__ void k_prep(const float* __restrict__ target, const float* __restrict__ Wf_w,
                       const float* __restrict__ Wf_b, const float* __restrict__ Wr2,
                       const float* __restrict__ bias_r, const float* __restrict__ Wr1) {
    int bx = blockIdx.x, t = threadIdx.x;
    if (bx < NB) {
        __shared__ float q[64];
        if (t < 64) {
            float a = Wf_b[t];
            const float* tg = target + bx * ND;
            const float* w = Wf_w + t * ND;
            #pragma unroll 8
            for (int d = 0; d < ND; d++) a += tg[d] * w[d];
            q[t] = a;
        }
        __syncthreads();
        float a = bias_r[t];
        const float* w2 = Wr2 + t * 64;
        #pragma unroll 8
        for (int e = 0; e < 64; e++) a += q[e] * w2[e];
        g_qb[bx * ND + t] = a;
    } else {
        for (int i = t; i < ND * ND; i += 128) {
            float x = Wr1[i];
            __nv_bfloat16 h = __float2bfloat16(x);
            g_Whi[i] = h;
            g_Wlo[i] = __float2bfloat16(x - __bfloat162float(h));
        }
    }
}

// ============ kernel 1: scores via mma.sync bf16 (3-product split) ============
// 512 threads (16 warps). CTA tile: 256 L-rows x 128 cols, K=128.
// Warp (wr=w>>2, wc=w&3): rows wr*64 (4 mtiles of 16), cols wc*32 (4 ntiles of 8).
// SMEM rows padded to 272 B (136 bf16) -> conflict-free ldmatrix.
#define ROWB 272
#define SA_HI 0
#define SA_LO 69632
#define SB_HI 139264
#define SB_LO 174080
#define SM_QB 208896
#define SM_W3 209408
#define SM_PART 209920
#define SM_TOTAL 214016

__global__ __launch_bounds__(512, 1)
void k_gemm(const float* __restrict__ R, const float* __restrict__ Wr3) {
    extern __shared__ char smem[];
    uint32_t sb = smem_u32(smem);
    int tid = threadIdx.x;
    int lane = tid & 31, w = tid >> 5;
    int wr = w >> 2, wc = w & 3;
    int b = blockIdx.y, l0 = blockIdx.x << 8;

    if (tid < 128) ((float*)(smem + SM_QB))[tid] = g_qb[b * ND + tid];
    else if (tid < 256) ((float*)(smem + SM_W3))[tid - 128] = Wr3[tid - 128];

    // ---- W tiles (bf16 hi/lo), coalesced + conflict-free ----
    {
        const uint4* wh = (const uint4*)g_Whi;
        const uint4* wl = (const uint4*)g_Wlo;
        #pragma unroll
        for (int i = 0; i < 4; i++) {
            int idx = tid + i * 512;              // 0..2047 uint4
            int r = idx >> 4, c = idx & 15;
            uint32_t off = r * ROWB + c * 16;
            *(uint4*)(smem + SB_HI + off) = wh[idx];
            *(uint4*)(smem + SB_LO + off) = wl[idx];
        }
    }
    // ---- A tile: R[b, l0:l0+256, :] fp32 -> bf16 hi/lo ----
    {
        const float4* src = (const float4*)(R + ((size_t)(b * NL + l0)) * ND);
        #pragma unroll
        for (int i = 0; i < 16; i++) {
            int idx = tid + i * 512;              // 0..8191 float4
            int row = idx >> 5, c4 = idx & 31;
            float4 v = src[idx];
            __nv_bfloat16 h0 = __float2bfloat16(v.x), h1 = __float2bfloat16(v.y);
            __nv_bfloat16 h2 = __float2bfloat16(v.z), h3 = __float2bfloat16(v.w);
            __nv_bfloat16 q0 = __float2bfloat16(v.x - __bfloat162float(h0));
            __nv_bfloat16 q1 = __float2bfloat16(v.y - __bfloat162float(h1));
            __nv_bfloat16 q2 = __float2bfloat16(v.z - __bfloat162float(h2));
            __nv_bfloat16 q3 = __float2bfloat16(v.w - __bfloat162float(h3));
            uint2 hp, lp;
            hp.x = ((uint32_t)__bfloat16_as_ushort(h1) << 16) | __bfloat16_as_ushort(h0);
            hp.y = ((uint32_t)__bfloat16_as_ushort(h3) << 16) | __bfloat16_as_ushort(h2);
            lp.x = ((uint32_t)__bfloat16_as_ushort(q1) << 16) | __bfloat16_as_ushort(q0);
            lp.y = ((uint32_t)__bfloat16_as_ushort(q3) << 16) | __bfloat16_as_ushort(q2);
            uint32_t off = row * ROWB + c4 * 8;
            *(uint2*)(smem + SA_HI + off) = hp;
            *(uint2*)(smem + SA_LO + off) = lp;
        }
    }
    __syncthreads();

    float acc[4][4][4];
    #pragma unroll
    for (int mt = 0; mt < 4; mt++)
        #pragma unroll
        for (int nt = 0; nt < 4; nt++)
            #pragma unroll
            for (int k = 0; k < 4; k++) acc[mt][nt][k] = 0.0f;

    // per-lane ldmatrix base addresses
    // A x4 (mtile): lanes 0-7 rows+0..7 k0 | 8-15 rows+8..15 k0 | 16-23 rows+0..7 k8 | 24-31 rows+8..15 k8
    uint32_t a_hi = sb + SA_HI + (wr * 64 + (lane & 15)) * ROWB + ((lane >> 4) * 8) * 2;
    uint32_t a_lo = a_hi + (SA_LO - SA_HI);
    // B x4 (ntile pair): lanes 0-7 nt0 k0 | 8-15 nt0 k8 | 16-23 nt1 k0 | 24-31 nt1 k8
    uint32_t b_hi = sb + SB_HI + (wc * 32 + (lane >> 4) * 8 + (lane & 7)) * ROWB
                    + (((lane >> 3) & 1) * 8) * 2;
    uint32_t b_lo = b_hi + (SB_LO - SB_HI);

    #pragma unroll
    for (int ks = 0; ks < 8; ks++) {
        uint32_t bh[4][2], bl[4][2];
        ldsm_x4(bh[0][0], bh[0][1], bh[1][0], bh[1][1], b_hi + ks * 32);
        ldsm_x4(bh[2][0], bh[2][1], bh[3][0], bh[3][1], b_hi + 16 * ROWB + ks * 32);
        ldsm_x4(bl[0][0], bl[0][1], bl[1][0], bl[1][1], b_lo + ks * 32);
        ldsm_x4(bl[2][0], bl[2][1], bl[3][0], bl[3][1], b_lo + 16 * ROWB + ks * 32);
        #pragma unroll
        for (int mt = 0; mt < 4; mt++) {
            uint32_t ah[4], al[4];
            ldsm_x4(ah[0], ah[1], ah[2], ah[3], a_hi + mt * 16 * ROWB + ks * 32);
            ldsm_x4(al[0], al[1], al[2], al[3], a_lo + mt * 16 * ROWB + ks * 32);
            #pragma unroll
            for (int nt = 0; nt < 4; nt++) {
                mma16816(acc[mt][nt], ah, bh[nt]);   // hi*hi
                mma16816(acc[mt][nt], ah, bl[nt]);   // hi*lo
                mma16816(acc[mt][nt], al, bh[nt]);   // lo*hi
            }
        }
    }

    // ---- fused epilogue: score[m] = sum_c relu(h[m,c]+qb[c]) * w3[c] ----
    {
        const float* qb = (const float*)(smem + SM_QB);
        const float* w3 = (const float*)(smem + SM_W3);
        float* part = (float*)(smem + SM_PART);
        int c0base = wc * 32 + (lane & 3) * 2;
        #pragma unroll
        for (int mt = 0; mt < 4; mt++) {
            float vlo = 0.0f, vhi = 0.0f;
            #pragma unroll
            for (int nt = 0; nt < 4; nt++) {
                int c0 = c0base + nt * 8, c1 = c0 + 1;
                float q0 = qb[c0], q1 = qb[c1], t0 = w3[c0], t1 = w3[c1];
                vlo += fmaxf(acc[mt][nt][0] + q0, 0.0f) * t0
                     + fmaxf(acc[mt][nt][1] + q1, 0.0f) * t1;
                vhi += fmaxf(acc[mt][nt][2] + q0, 0.0f) * t0
                     + fmaxf(acc[mt][nt][3] + q1, 0.0f) * t1;
            }
            vlo += __shfl_xor_sync(0xFFFFFFFFu, vlo, 1);
            vlo += __shfl_xor_sync(0xFFFFFFFFu, vlo, 2);
            vhi += __shfl_xor_sync(0xFFFFFFFFu, vhi, 1);
            vhi += __shfl_xor_sync(0xFFFFFFFFu, vhi, 2);
            if ((lane & 3) == 0) {
                int rlo = wr * 64 + mt * 16 + (lane >> 2);
                part[rlo * 4 + wc] = vlo;
                part[(rlo + 8) * 4 + wc] = vhi;
            }
        }
        __syncthreads();
        if (tid < 256) {
            float s = part[tid * 4] + part[tid * 4 + 1] + part[tid * 4 + 2] + part[tid * 4 + 3];
            g_scores[b * NL + l0 + tid] = s;
        }
    }
}

// ============ kernel 2: entmax bisection + sparse weighted sum + selu + normalize ============
__device__ __forceinline__ float block_sum512(float v, volatile float* red) {
    #pragma unroll
    for (int o = 16; o; o >>= 1) v += __shfl_xor_sync(0xFFFFFFFFu, v, o);
    int w = threadIdx.x >> 5;
    if ((threadIdx.x & 31) == 0) red[w] = v;
    __syncthreads();
    if (threadIdx.x < 32) {
        float s = (threadIdx.x < 16) ? red[threadIdx.x] : 0.0f;
        #pragma unroll
        for (int o = 16; o; o >>= 1) s += __shfl_xor_sync(0xFFFFFFFFu, s, o);
        if (threadIdx.x == 0) red[16] = s;
    }
    __syncthreads();
    float s = red[16];
    __syncthreads();
    return s;
}
__device__ __forceinline__ float block_max512(float v, volatile float* red) {
    #pragma unroll
    for (int o = 16; o; o >>= 1) v = fmaxf(v, __shfl_xor_sync(0xFFFFFFFFu, v, o));
    int w = threadIdx.x >> 5;
    if ((threadIdx.x & 31) == 0) red[w] = v;
    __syncthreads();
    if (threadIdx.x < 32) {
        float s = (threadIdx.x < 16) ? red[threadIdx.x] : -3.4e38f;
        #pragma unroll
        for (int o = 16; o; o >>= 1) s = fmaxf(s, __shfl_xor_sync(0xFFFFFFFFu, s, o));
        if (threadIdx.x == 0) red[16] = s;
    }
    __syncthreads();
    float s = red[16];
    __syncthreads();
    return s;
}

__global__ __launch_bounds__(512, 1)
void k_entmax(const float* __restrict__ R, const float* __restrict__ alpha,
              float* __restrict__ out) {
    __shared__ float xs[NL];
    __shared__ float red[17];
    __shared__ float part[512];
    __shared__ float sr[ND];
    __shared__ float nrm;

    int b = blockIdx.x, t = threadIdx.x;
    float am1 = alpha[b] - 1.0f;
    float inv = 1.0f / am1;

    float mx = -3.4e38f;
    #pragma unroll
    for (int i = 0; i < 8; i++) {
        int l = t + i * 512;
        float v = g_scores[b * NL + l] * am1;
        xs[l] = v;
        mx = fmaxf(mx, v);
    }
    __syncthreads();
    mx = block_max512(mx, red);

    float tau_lo = mx - 1.0f;
    float tau_hi = mx - powf(1.0f / (float)NL, am1);
    float dm = tau_hi - tau_lo;

    float local = 0.0f;
    #pragma unroll
    for (int i = 0; i < 8; i++) {
        float x = xs[t + i * 512] - tau_lo;
        if (x > 0.0f) local += powf(x, inv);
    }
    float f_lo = block_sum512(local, red) - 1.0f;

    float tau_m = tau_lo;
    for (int it = 0; it < 50; it++) {
        dm *= 0.5f;
        tau_m = tau_lo + dm;
        local = 0.0f;
        #pragma unroll
        for (int i = 0; i < 8; i++) {
            float x = xs[t + i * 512] - tau_m;
            if (x > 0.0f) local += powf(x, inv);
        }
        float f_m = block_sum512(local, red) - 1.0f;
        if (f_m * f_lo >= 0.0f) tau_lo = tau_m;
    }

    local = 0.0f;
    #pragma unroll
    for (int i = 0; i < 8; i++) {
        int l = t + i * 512;
        float x = xs[l] - tau_m;
        float p = (x > 0.0f) ? powf(x, inv) : 0.0f;
        xs[l] = p;
        local += p;
    }
    float S = block_sum512(local, red);
    float invS = 1.0f / S;

    // sparse weighted sum: thread t -> d = t&127, quarter = t>>7 (l warp-uniform)
    int q4 = t >> 7, d = t & 127;
    const float* Rb = R + (size_t)b * NL * ND;
    float acc = 0.0f;
    for (int i = 0; i < 1024; i++) {
        int l = q4 * 1024 + i;
        float wv = xs[l];
        if (wv != 0.0f) acc += wv * Rb[(size_t)l * ND + d];
    }
    part[t] = acc;
    __syncthreads();

    if (t < ND) {
        float r = (part[t] + part[128 + t] + part[256 + t] + part[384 + t]) * invS;
        float s = (r > 0.0f) ? r : 1.6732632423543772f * expm1f(r);
        sr[t] = 1.0507009873554805f * s;
    }
    __syncthreads();
    if (t == 0) {
        float s = 0.0f;
        for (int d2 = 0; d2 < ND; d2++) s += sr[d2] * sr[d2];
        nrm = 1.0f / sqrtf(s);
    }
    __syncthreads();
    if (t < ND) out[b * ND + t] = sr[t] * nrm;
}

// ============ launch ============
extern "C" void kernel_launch(void* const* d_in, const int* in_sizes, int n_in,
                              void* d_out, int out_size) {
    const float* R      = (const float*)d_in[0];
    const float* alpha  = (const float*)d_in[1];
    const float* target = (const float*)d_in[2];
    const float* Wr1    = (const float*)d_in[3];
    const float* Wr2    = (const float*)d_in[4];
    const float* Wr3    = (const float*)d_in[5];
    const float* bias_r = (const float*)d_in[6];
    const float* Wf_w   = (const float*)d_in[7];
    const float* Wf_b   = (const float*)d_in[8];
    float* out = (float*)d_out;

    cudaFuncSetAttribute(k_gemm, cudaFuncAttributeMaxDynamicSharedMemorySize, SM_TOTAL);

    k_prep<<<NB + 1, 128>>>(target, Wf_w, Wf_b, Wr2, bias_r, Wr1);
    dim3 g1(NL / 256, NB);
    k_gemm<<<g1, 512, SM_TOTAL>>>(R, Wr3);
    k_entmax<<<NB, 512>>>(R, alpha, out);
}

// round 7
// speedup vs baseline: 1.1386x; 1.1386x over previous
#include <cuda_runtime.h>
#include <cuda_bf16.h>
#include <cstdint>
#include <math.h>

#define NB 128
#define NL 4096
#define ND 128
#define NTILES 4096   // 128-row L tiles: NB * (NL/128)

// ---------------- scratch (device globals; no allocation) ----------------
__device__ float          g_qb[NB * ND];
__device__ __nv_bfloat16  g_Whi[ND * ND];
__device__ __nv_bfloat16  g_Wlo[ND * ND];
__device__ float          g_scores[NB * NL];

__device__ __forceinline__ uint32_t smem_u32(const void* p) {
    uint32_t a;
    asm("{ .reg .u64 t; cvta.to.shared.u64 t, %1; cvt.u32.u64 %0, t; }" : "=r"(a) : "l"(p));
    return a;
}
__device__ __forceinline__ void ldsm_x4(uint32_t& r0, uint32_t& r1, uint32_t& r2, uint32_t& r3,
                                        uint32_t addr) {
    asm volatile("ldmatrix.sync.aligned.m8n8.x4.shared.b16 {%0,%1,%2,%3}, [%4];"
                 : "=r"(r0), "=r"(r1), "=r"(r2), "=r"(r3) : "r"(addr));
}
__device__ __forceinline__ void mma16816(float* c, const uint32_t* a, const uint32_t* b) {
    asm volatile("mma.sync.aligned.m16n8k16.row.col.f32.bf16.bf16.f32 "
                 "{%0,%1,%2,%3}, {%4,%5,%6,%7}, {%8,%9}, {%0,%1,%2,%3};"
                 : "+f"(c[0]), "+f"(c[1]), "+f"(c[2]), "+f"(c[3])
                 : "r"(a[0]), "r"(a[1]), "r"(a[2]), "r"(a[3]), "r"(b[0]), "r"(b[1]));
}
// fast pow via MUFU: x^e = 2^(e * log2 x), x > 0
__device__ __forceinline__ float fast_pow(float x, float e) {
    float l, r;
    asm("lg2.approx.f32 %0, %1;" : "=f"(l) : "f"(x));
    l *= e;
    asm("ex2.approx.f32 %0, %1;" : "=f"(r) : "f"(l));
    return r;
}

// ============ kernel 0: qb = Wr2·(Wf target + b) + bias_r ; Wr1 -> hi/lo bf16 ============
__global__ void k_prep(const float* __restrict__ target, const float* __restrict__ Wf_w,
                       const float* __restrict__ Wf_b, const float* __restrict__ Wr2,
                       const float* __restrict__ bias_r, const float* __restrict__ Wr1) {
    int bx = blockIdx.x, t = threadIdx.x;
    int lane = t & 31, w = t >> 5;
    if (bx < NB) {
        __shared__ float q[64];
        // stage 1: q[e] = Wf_b[e] + dot128(target[bx], Wf_w[e])  (warp-cooperative)
        float4 tg4 = ((const float4*)(target + bx * ND))[lane];
        for (int e = w; e < 64; e += 4) {
            float4 wf = ((const float4*)(Wf_w + e * ND))[lane];
            float p = tg4.x * wf.x + tg4.y * wf.y + tg4.z * wf.z + tg4.w * wf.w;
            #pragma unroll
            for (int o = 16; o; o >>= 1) p += __shfl_xor_sync(0xFFFFFFFFu, p, o);
            if (lane == 0) q[e] = p + Wf_b[e];
        }
        __syncthreads();
        // stage 2: qb[d] = bias_r[d] + dot64(q, Wr2[d])
        float2 q2 = ((const float2*)q)[lane];
        for (int d = w; d < ND; d += 4) {
            float2 w2 = ((const float2*)(Wr2 + d * 64))[lane];
            float p = q2.x * w2.x + q2.y * w2.y;
            #pragma unroll
            for (int o = 16; o; o >>= 1) p += __shfl_xor_sync(0xFFFFFFFFu, p, o);
            if (lane == 0) g_qb[bx * ND + d] = p + bias_r[d];
        }
    } else {
        const float4* src = (const float4*)Wr1;
        uint2* dhi = (uint2*)g_Whi;
        uint2* dlo = (uint2*)g_Wlo;
        for (int i = t; i < ND * ND / 4; i += 128) {
            float4 v = src[i];
            __nv_bfloat16 h0 = __float2bfloat16(v.x), h1 = __float2bfloat16(v.y);
            __nv_bfloat16 h2 = __float2bfloat16(v.z), h3 = __float2bfloat16(v.w);
            __nv_bfloat16 q0 = __float2bfloat16(v.x - __bfloat162float(h0));
            __nv_bfloat16 q1 = __float2bfloat16(v.y - __bfloat162float(h1));
            __nv_bfloat16 q2 = __float2bfloat16(v.z - __bfloat162float(h2));
            __nv_bfloat16 q3 = __float2bfloat16(v.w - __bfloat162float(h3));
            uint2 hp, lp;
            hp.x = ((uint32_t)__bfloat16_as_ushort(h1) << 16) | __bfloat16_as_ushort(h0);
            hp.y = ((uint32_t)__bfloat16_as_ushort(h3) << 16) | __bfloat16_as_ushort(h2);
            lp.x = ((uint32_t)__bfloat16_as_ushort(q1) << 16) | __bfloat16_as_ushort(q0);
            lp.y = ((uint32_t)__bfloat16_as_ushort(q3) << 16) | __bfloat16_as_ushort(q2);
            dhi[i] = hp;
            dlo[i] = lp;
        }
    }
}

// ============ kernel 1: persistent split-bf16 GEMM + fused score epilogue ============
// 512 threads (16 warps), 128-row tiles. Warp tile 32x32 (wr=w>>2 rows, wc=w&3 cols).
// SMEM rows padded to 272 B -> conflict-free ldmatrix.
#define ROWB 272
#define SA_HI 0
#define SA_LO 34816
#define SB_HI 69632
#define SB_LO 104448
#define SM_PART 139264
#define SM_W3   141312
#define SM_TOTAL 141824

__device__ __forceinline__ void ldg_tile(float4* v, const float* __restrict__ R,
                                         int tile, int tid) {
    int b = tile >> 5, l0 = (tile & 31) << 7;
    const float4* src = (const float4*)(R + ((size_t)b * NL + l0) * ND);
    #pragma unroll
    for (int i = 0; i < 8; i++) v[i] = src[tid + i * 512];
}
__device__ __forceinline__ void cvt_store(char* smem, const float4* v, int tid) {
    #pragma unroll
    for (int i = 0; i < 8; i++) {
        int idx = tid + i * 512;
        int row = idx >> 5, c4 = idx & 31;
        float4 x = v[i];
        __nv_bfloat16 h0 = __float2bfloat16(x.x), h1 = __float2bfloat16(x.y);
        __nv_bfloat16 h2 = __float2bfloat16(x.z), h3 = __float2bfloat16(x.w);
        __nv_bfloat16 q0 = __float2bfloat16(x.x - __bfloat162float(h0));
        __nv_bfloat16 q1 = __float2bfloat16(x.y - __bfloat162float(h1));
        __nv_bfloat16 q2 = __float2bfloat16(x.z - __bfloat162float(h2));
        __nv_bfloat16 q3 = __float2bfloat16(x.w - __bfloat162float(h3));
        uint2 hp, lp;
        hp.x = ((uint32_t)__bfloat16_as_ushort(h1) << 16) | __bfloat16_as_ushort(h0);
        hp.y = ((uint32_t)__bfloat16_as_ushort(h3) << 16) | __bfloat16_as_ushort(h2);
        lp.x = ((uint32_t)__bfloat16_as_ushort(q1) << 16) | __bfloat16_as_ushort(q0);
        lp.y = ((uint32_t)__bfloat16_as_ushort(q3) << 16) | __bfloat16_as_ushort(q2);
        uint32_t off = row * ROWB + c4 * 8;
        *(uint2*)(smem + SA_HI + off) = hp;
        *(uint2*)(smem + SA_LO + off) = lp;
    }
}

__global__ __launch_bounds__(512, 1)
void k_gemm(const float* __restrict__ R, const float* __restrict__ Wr3) {
    extern __shared__ char smem[];
    uint32_t sb = smem_u32(smem);
    int tid = threadIdx.x, lane = tid & 31, w = tid >> 5;
    int wr = w >> 2, wc = w & 3;

    // ---- W tiles once per CTA ----
    {
        const uint4* wh = (const uint4*)g_Whi;
        const uint4* wl = (const uint4*)g_Wlo;
        #pragma unroll
        for (int i = 0; i < 4; i++) {
            int idx = tid + i * 512;               // 0..2047 uint4
            int r = idx >> 4, c = idx & 15;
            uint32_t off = r * ROWB + c * 16;
            *(uint4*)(smem + SB_HI + off) = wh[idx];
            *(uint4*)(smem + SB_LO + off) = wl[idx];
        }
        if (tid < ND) ((float*)(smem + SM_W3))[tid] = Wr3[tid];
    }

    uint32_t a_hi = sb + SA_HI + (wr * 32 + (lane & 15)) * ROWB + (lane >> 4) * 16;
    uint32_t a_lo = a_hi + (SA_LO - SA_HI);
    uint32_t b_hi = sb + SB_HI + (wc * 32 + (lane >> 4) * 8 + (lane & 7)) * ROWB
                    + ((lane >> 3) & 1) * 16;
    uint32_t b_lo = b_hi + (SB_LO - SB_HI);

    int stride = gridDim.x;
    int t = blockIdx.x;
    float4 v[8];
    if (t < NTILES) {
        ldg_tile(v, R, t, tid);
        cvt_store(smem, v, tid);
    }

    while (t < NTILES) {
        __syncthreads();                            // A (and first-iter B) visible
        int tn = t + stride;
        if (tn < NTILES) ldg_tile(v, R, tn, tid);   // register prefetch of next tile

        int b = t >> 5, l0 = (t & 31) << 7;

        float acc[2][4][4];
        #pragma unroll
        for (int mt = 0; mt < 2; mt++)
            #pragma unroll
            for (int nt = 0; nt < 4; nt++)
                #pragma unroll
                for (int k = 0; k < 4; k++) acc[mt][nt][k] = 0.0f;

        #pragma unroll
        for (int ks = 0; ks < 8; ks++) {
            uint32_t bh[4][2], bl[4][2];
            ldsm_x4(bh[0][0], bh[0][1], bh[1][0], bh[1][1], b_hi + ks * 32);
            ldsm_x4(bh[2][0], bh[2][1], bh[3][0], bh[3][1], b_hi + 16 * ROWB + ks * 32);
            ldsm_x4(bl[0][0], bl[0][1], bl[1][0], bl[1][1], b_lo + ks * 32);
            ldsm_x4(bl[2][0], bl[2][1], bl[3][0], bl[3][1], b_lo + 16 * ROWB + ks * 32);
            #pragma unroll
            for (int mt = 0; mt < 2; mt++) {
                uint32_t ah[4], al[4];
                ldsm_x4(ah[0], ah[1], ah[2], ah[3], a_hi + mt * 16 * ROWB + ks * 32);
                ldsm_x4(al[0], al[1], al[2], al[3], a_lo + mt * 16 * ROWB + ks * 32);
                #pragma unroll
                for (int nt = 0; nt < 4; nt++) {
                    mma16816(acc[mt][nt], ah, bh[nt]);
                    mma16816(acc[mt][nt], ah, bl[nt]);
                    mma16816(acc[mt][nt], al, bh[nt]);
                }
            }
        }

        // fused epilogue: score[m] = sum_c relu(h+qb)*w3
        {
            const float* w3s = (const float*)(smem + SM_W3);
            float* part = (float*)(smem + SM_PART);
            const float* qbb = g_qb + b * ND;
            int c0base = wc * 32 + (lane & 3) * 2;
            #pragma unroll
            for (int mt = 0; mt < 2; mt++) {
                float vlo = 0.0f, vhi = 0.0f;
                #pragma unroll
                for (int nt = 0; nt < 4; nt++) {
                    int c0 = c0base + nt * 8, c1 = c0 + 1;
                    float q0 = __ldg(qbb + c0), q1 = __ldg(qbb + c1);
                    float t0 = w3s[c0], t1 = w3s[c1];
                    vlo += fmaxf(acc[mt][nt][0] + q0, 0.0f) * t0
                         + fmaxf(acc[mt][nt][1] + q1, 0.0f) * t1;
                    vhi += fmaxf(acc[mt][nt][2] + q0, 0.0f) * t0
                         + fmaxf(acc[mt][nt][3] + q1, 0.0f) * t1;
                }
                vlo += __shfl_xor_sync(0xFFFFFFFFu, vlo, 1);
                vlo += __shfl_xor_sync(0xFFFFFFFFu, vlo, 2);
                vhi += __shfl_xor_sync(0xFFFFFFFFu, vhi, 1);
                vhi += __shfl_xor_sync(0xFFFFFFFFu, vhi, 2);
                if ((lane & 3) == 0) {
                    int rlo = wr * 32 + mt * 16 + (lane >> 2);
                    part[rlo * 4 + wc] = vlo;
                    part[(rlo + 8) * 4 + wc] = vhi;
                }
            }
        }
        __syncthreads();                            // part ready; ldsm of this tile done
        if (tid < 128) {
            const float* part = (const float*)(smem + SM_PART);
            float s = part[tid * 4] + part[tid * 4 + 1] + part[tid * 4 + 2] + part[tid * 4 + 3];
            g_scores[b * NL + l0 + tid] = s;
        }
        if (tn < NTILES) cvt_store(smem, v, tid);   // fill A for next tile
        t = tn;
    }
}

// ============ kernel 2: entmax bisection (candidate-compacted) + sparse sum ============
__global__ __launch_bounds__(512, 1)
void k_entmax(const float* __restrict__ R, const float* __restrict__ alpha,
              float* __restrict__ out) {
    __shared__ float cval[NL];
    __shared__ unsigned short cidx[NL];
    __shared__ float red[16];
    __shared__ int cnt;
    __shared__ float part[512];

    int b = blockIdx.x, t = threadIdx.x;
    int lane = t & 31, w = t >> 5;
    float am1 = alpha[b] - 1.0f;
    float inv = 1.0f / am1;

    if (t == 0) cnt = 0;

    // load scores, scale, find max
    float v[8];
    float mx = -3.4e38f;
    #pragma unroll
    for (int i = 0; i < 8; i++) {
        v[i] = g_scores[b * NL + t + i * 512] * am1;
        mx = fmaxf(mx, v[i]);
    }
    #pragma unroll
    for (int o = 16; o; o >>= 1) mx = fmaxf(mx, __shfl_xor_sync(0xFFFFFFFFu, mx, o));
    if (lane == 0) red[w] = mx;
    __syncthreads();
    mx = red[0];
    #pragma unroll
    for (int i = 1; i < 16; i++) mx = fmaxf(mx, red[i]);
    __syncthreads();

    // compact candidates: only Xs > mx-1 can ever have p > 0 (tau >= mx-1 always)
    float thr = mx - 1.0f;
    #pragma unroll
    for (int i = 0; i < 8; i++) {
        bool p = v[i] > thr;
        unsigned m = __ballot_sync(0xFFFFFFFFu, p);
        int base = 0;
        if (lane == 0 && m) base = atomicAdd(&cnt, __popc(m));
        base = __shfl_sync(0xFFFFFFFFu, base, 0);
        if (p) {
            int off = base + __popc(m & ((1u << lane) - 1u));
            cval[off] = v[i];
            cidx[off] = (unsigned short)(t + i * 512);
        }
    }
    __syncthreads();
    int K = cnt;

    // bisection (same 50-iter trajectory as reference; MUFU pow)
    float tau_lo = mx - 1.0f;
    float tau_hi = mx - exp2f(-12.0f * am1);       // (1/4096)^am1
    float dm = tau_hi - tau_lo;

    float s = 0.0f;
    for (int j = t; j < K; j += 512) {
        float x = cval[j] - tau_lo;
        if (x > 0.0f) s += fast_pow(x, inv);
    }
    #pragma unroll
    for (int o = 16; o; o >>= 1) s += __shfl_xor_sync(0xFFFFFFFFu, s, o);
    if (lane == 0) red[w] = s;
    __syncthreads();
    float f_lo = -1.0f;
    #pragma unroll
    for (int i = 0; i < 16; i++) f_lo += red[i];
    __syncthreads();

    float tau_m = tau_lo;
    for (int it = 0; it < 50; it++) {
        dm *= 0.5f;
        tau_m = tau_lo + dm;
        s = 0.0f;
        for (int j = t; j < K; j += 512) {
            float x = cval[j] - tau_m;
            if (x > 0.0f) s += fast_pow(x, inv);
        }
        #pragma unroll
        for (int o = 16; o; o >>= 1) s += __shfl_xor_sync(0xFFFFFFFFu, s, o);
        if (lane == 0) red[w] = s;
        __syncthreads();
        float f_m = -1.0f;
        #pragma unroll
        for (int i = 0; i < 16; i++) f_m += red[i];
        __syncthreads();
        if (f_m * f_lo >= 0.0f) tau_lo = tau_m;
    }

    // final p and its sum (overwrite cval with p)
    s = 0.0f;
    for (int j = t; j < K; j += 512) {
        float x = cval[j] - tau_m;
        float p = (x > 0.0f) ? fast_pow(x, inv) : 0.0f;
        cval[j] = p;
        s += p;
    }
    #pragma unroll
    for (int o = 16; o; o >>= 1) s += __shfl_xor_sync(0xFFFFFFFFu, s, o);
    if (lane == 0) red[w] = s;
    __syncthreads();
    float S = 0.0f;
    #pragma unroll
    for (int i = 0; i < 16; i++) S += red[i];
    __syncthreads();
    float invS = 1.0f / S;

    // sparse weighted sum over candidates only: group g handles j = g mod 4
    int g = t >> 7, d = t & 127;
    const float* Rb = R + (size_t)b * NL * ND;
    float acc = 0.0f;
    for (int j = g; j < K; j += 4) {
        float wv = cval[j];
        if (wv != 0.0f) {
            int l = cidx[j];
            acc += wv * Rb[(size_t)l * ND + d];
        }
    }
    part[t] = acc;
    __syncthreads();

    float myr = 0.0f;
    if (t < ND) {
        float r = (part[t] + part[128 + t] + part[256 + t] + part[384 + t]) * invS;
        float e = (r > 0.0f) ? r : 1.6732632423543772f * expm1f(r);
        myr = 1.0507009873554805f * e;
    }
    // L2 norm
    float nsq = myr * myr;
    #pragma unroll
    for (int o = 16; o; o >>= 1) nsq += __shfl_xor_sync(0xFFFFFFFFu, nsq, o);
    if (lane == 0) red[w] = nsq;
    __syncthreads();
    float tot = 0.0f;
    #pragma unroll
    for (int i = 0; i < 16; i++) tot += red[i];
    if (t < ND) out[b * ND + t] = myr / sqrtf(tot);
}

// ============ launch ============
extern "C" void kernel_launch(void* const* d_in, const int* in_sizes, int n_in,
                              void* d_out, int out_size) {
    const float* R      = (const float*)d_in[0];
    const float* alpha  = (const float*)d_in[1];
    const float* target = (const float*)d_in[2];
    const float* Wr1    = (const float*)d_in[3];
    const float* Wr2    = (const float*)d_in[4];
    const float* Wr3    = (const float*)d_in[5];
    const float* bias_r = (const float*)d_in[6];
    const float* Wf_w   = (const float*)d_in[7];
    const float* Wf_b   = (const float*)d_in[8];
    float* out = (float*)d_out;

    int nsm = 0;
    cudaDeviceGetAttribute(&nsm, cudaDevAttrMultiProcessorCount, 0);
    if (nsm <= 0) nsm = 148;

    cudaFuncSetAttribute(k_gemm, cudaFuncAttributeMaxDynamicSharedMemorySize, SM_TOTAL);

    k_prep<<<NB + 1, 128>>>(target, Wf_w, Wf_b, Wr2, bias_r, Wr1);
    k_gemm<<<nsm, 512, SM_TOTAL>>>(R, Wr3);
    k_entmax<<<NB, 512>>>(R, alpha, out);
}